// round 4
// baseline (speedup 1.0000x reference)
#include <cuda_runtime.h>
#include <math.h>

#define NN 100000
#define EE 800000
#define ET (EE + NN)
#define HID 128
#define H2 192
#define G4 768

// ------------------------- scratch (static device globals) -------------------------
__device__ float g_x0[2][NN * HID];          // initial embeddings per branch
__device__ float g_xs[2][3][NN * HID];       // per-layer conv outputs per branch
__device__ float g_mean[NN * HID];           // 0.5*(x_l + x_r) of layer inputs
__device__ float g_xh[NN * 256];             // x @ W   [N, heads*hid]
__device__ float g_gat[NN * 256];            // scatter accumulator [N, heads, hid]
__device__ float g_asrc[NN * 2];
__device__ float g_adst[NN * 2];
__device__ unsigned g_mmax[NN * 2];          // encoded segment max
__device__ float g_den[NN * 2];              // segment softmax denominator
__device__ int g_src[2][ET];
__device__ int g_dst[2][ET];
__device__ float g_eval[ET * 2];             // edge logits -> exp values
__device__ float g_G[(size_t)NN * G4];       // LSTM gate pre-activations
__device__ float g_h[NN * H2];
__device__ float g_c[NN * H2];
__device__ float g_s[3 * NN];                // JK attention logits
__device__ float g_jk[2][NN * HID];
__device__ float g_sq[2][NN * HID];
__device__ float g_outs[4][NN * HID];

__device__ __forceinline__ float sigm(float x) { return 1.0f / (1.0f + expf(-x)); }

// ------------------------- tiled SGEMM: 128x128x8 block, 8x8/thread, double-buffered -------------------------
// C[M,Nn] = A[M,K] * op(B) (+ bias) (+ C).  TRANSB: B is [Nn,K] row-major.
// Requires K%8==0, Nn%128==0 (call sites: K in {128,192}, Nn in {128,256,768}).
template <int TRANSB, int ACC, int BIAS>
__global__ __launch_bounds__(256) void sgemm_kernel(
    const float* __restrict__ A, const float* __restrict__ B,
    const float* __restrict__ bias, float* __restrict__ C,
    int M, int Nn, int K) {
    __shared__ float As[8][136];
    __shared__ float Bs[8][136];
    int tid = threadIdx.x;
    int bm = blockIdx.y * 128;
    int bn = blockIdx.x * 128;
    int tr = tid >> 4, tc = tid & 15;   // 16x16 threads, each 8x8 outputs
    float acc[8][8] = {};

    // per-thread load coordinates
    const int am = tid >> 1, ak = (tid & 1) << 2;      // A: row, k-offset
    const int gm_a = bm + am;
    int bk, bn_off;                                     // B coords
    if (!TRANSB) { bk = tid >> 5; bn_off = (tid & 31) << 2; }
    else         { bk = (tid & 1) << 2; bn_off = tid >> 1; }

    // prefetch tile 0 into registers
    float4 a_reg = make_float4(0.f, 0.f, 0.f, 0.f), b_reg;
    if (gm_a < M) a_reg = *(const float4*)(A + (size_t)gm_a * K + ak);
    if (!TRANSB) b_reg = *(const float4*)(B + (size_t)bk * Nn + bn + bn_off);
    else         b_reg = *(const float4*)(B + (size_t)(bn + bn_off) * K + bk);

    for (int k0 = 0; k0 < K; k0 += 8) {
        // commit current registers to smem
        As[ak][am] = a_reg.x; As[ak + 1][am] = a_reg.y;
        As[ak + 2][am] = a_reg.z; As[ak + 3][am] = a_reg.w;
        if (!TRANSB) {
            Bs[bk][bn_off] = b_reg.x; Bs[bk][bn_off + 1] = b_reg.y;
            Bs[bk][bn_off + 2] = b_reg.z; Bs[bk][bn_off + 3] = b_reg.w;
        } else {
            Bs[bk][bn_off] = b_reg.x; Bs[bk + 1][bn_off] = b_reg.y;
            Bs[bk + 2][bn_off] = b_reg.z; Bs[bk + 3][bn_off] = b_reg.w;
        }
        __syncthreads();

        // prefetch next tile (overlaps with compute below)
        int k1 = k0 + 8;
        if (k1 < K) {
            if (gm_a < M) a_reg = *(const float4*)(A + (size_t)gm_a * K + k1 + ak);
            if (!TRANSB) b_reg = *(const float4*)(B + (size_t)(k1 + bk) * Nn + bn + bn_off);
            else         b_reg = *(const float4*)(B + (size_t)(bn + bn_off) * K + k1 + bk);
        }

#pragma unroll
        for (int k = 0; k < 8; k++) {
            float a[8], b[8];
#pragma unroll
            for (int i = 0; i < 8; i++) a[i] = As[k][tr * 8 + i];
#pragma unroll
            for (int j = 0; j < 8; j++) b[j] = Bs[k][tc * 8 + j];
#pragma unroll
            for (int i = 0; i < 8; i++)
#pragma unroll
                for (int j = 0; j < 8; j++) acc[i][j] += a[i] * b[j];
        }
        __syncthreads();
    }
#pragma unroll
    for (int i = 0; i < 8; i++) {
        int gm = bm + tr * 8 + i;
        if (gm < M) {
            float* crow = C + (size_t)gm * Nn + bn + tc * 8;
#pragma unroll
            for (int j = 0; j < 8; j++) {
                float v = acc[i][j];
                if (BIAS) v += bias[bn + tc * 8 + j];
                if (ACC) v += crow[j];
                crow[j] = v;
            }
        }
    }
}

// ------------------------- pointwise / graph kernels -------------------------
__global__ void embed_kernel(const int* __restrict__ x_idx, const float* __restrict__ x_flt,
                             const float* __restrict__ emb_aa, const float* __restrict__ emb_ss) {
    int idx = blockIdx.x * 256 + threadIdx.x;
    if (idx >= 2 * NN * HID) return;
    int br = idx / (NN * HID);
    int r = idx - br * (NN * HID);
    int n = r >> 7, c = r & 127;
    float v;
    if (c < 123) {
        int ai = x_idx[n * 2], si = x_idx[n * 2 + 1];
        v = emb_aa[((size_t)br * 26 + ai) * 123 + c] + emb_ss[((size_t)br * 3 + si) * 123 + c];
    } else {
        v = x_flt[n * 5 + (c - 123)];
    }
    g_x0[br][r] = v;
}

__global__ void build_edges(const int* __restrict__ el, const int* __restrict__ er) {
    int i = blockIdx.x * 256 + threadIdx.x;
    if (i >= ET) return;
    int sl, dl, sr, dr;
    if (i < EE) { sl = el[i]; dl = el[EE + i]; sr = er[i]; dr = er[EE + i]; }
    else { sl = dl = sr = dr = i - EE; }
    g_src[0][i] = sl; g_dst[0][i] = dl;
    g_src[1][i] = sr; g_dst[1][i] = dr;
}

__global__ void mean_kernel(const float* __restrict__ xl, const float* __restrict__ xr) {
    int idx = blockIdx.x * 256 + threadIdx.x;
    if (idx >= NN * HID) return;
    g_mean[idx] = 0.5f * (xl[idx] + xr[idx]);
}

__global__ void att_kernel(const float* __restrict__ aw_src, const float* __restrict__ aw_dst) {
    int n = blockIdx.x, t = threadIdx.x;
    __shared__ float rs[256], rd[256];
    float v = g_xh[(size_t)n * 256 + t];
    rs[t] = v * aw_src[t];
    rd[t] = v * aw_dst[t];
    __syncthreads();
    int h = t >> 7, c = t & 127;
    for (int st = 64; st > 0; st >>= 1) {
        if (c < st) { rs[t] += rs[t + st]; rd[t] += rd[t + st]; }
        __syncthreads();
    }
    if (c == 0) { g_asrc[n * 2 + h] = rs[t]; g_adst[n * 2 + h] = rd[t]; }
}

__global__ void clear_conv() {
    int idx = blockIdx.x * 256 + threadIdx.x;
    if (idx < NN * 256) g_gat[idx] = 0.f;
    if (idx < NN * 2) { g_mmax[idx] = 0u; g_den[idx] = 0.f; }
}

__device__ __forceinline__ unsigned enc_f(float v) {
    unsigned u = __float_as_uint(v);
    return (u & 0x80000000u) ? ~u : (u | 0x80000000u);
}
__device__ __forceinline__ float dec_f(unsigned e) {
    unsigned u = (e & 0x80000000u) ? (e ^ 0x80000000u) : ~e;
    return __uint_as_float(u);
}

__global__ void edge_passA(int br) {
    int e = blockIdx.x * 256 + threadIdx.x;
    if (e >= ET) return;
    int s = g_src[br][e], d = g_dst[br][e];
#pragma unroll
    for (int h = 0; h < 2; h++) {
        float v = g_asrc[s * 2 + h] + g_adst[d * 2 + h];
        v = v > 0.f ? v : 0.2f * v;   // leaky_relu(0.2)
        g_eval[e * 2 + h] = v;
        atomicMax(&g_mmax[d * 2 + h], enc_f(v));
    }
}

__global__ void edge_passB(int br) {
    int e = blockIdx.x * 256 + threadIdx.x;
    if (e >= ET) return;
    int d = g_dst[br][e];
#pragma unroll
    for (int h = 0; h < 2; h++) {
        float m = dec_f(g_mmax[d * 2 + h]);
        float ex = expf(g_eval[e * 2 + h] - m);
        g_eval[e * 2 + h] = ex;
        atomicAdd(&g_den[d * 2 + h], ex);
    }
}

// 4 edges per block: 256 threads each sweep full 256-channel row per edge.
__global__ __launch_bounds__(256) void edge_passC(int br) {
    int t = threadIdx.x;
    int h = t >> 7;
    int e0 = blockIdx.x * 4;
#pragma unroll
    for (int sub = 0; sub < 4; sub++) {
        int e = e0 + sub;
        if (e >= ET) return;
        int s = g_src[br][e], d = g_dst[br][e];
        float alpha = g_eval[e * 2 + h] / (g_den[d * 2 + h] + 1e-16f);
        atomicAdd(&g_gat[(size_t)d * 256 + t], g_xh[(size_t)s * 256 + t] * alpha);
    }
}

__global__ void finalize_conv(int br, int layer, const float* __restrict__ bias) {
    int idx = blockIdx.x * 256 + threadIdx.x;
    if (idx >= NN * HID) return;
    int n = idx >> 7, c = idx & 127;
    float gm = 0.5f * (g_gat[(size_t)n * 256 + c] + g_gat[(size_t)n * 256 + 128 + c]) + bias[c];
    g_xs[br][layer][idx] = g_mean[idx] + fmaxf(gm, 0.f);
}

__global__ void clear_hc() {
    int idx = blockIdx.x * 256 + threadIdx.x;
    if (idx >= NN * H2) return;
    g_h[idx] = 0.f;
    g_c[idx] = 0.f;
}

__global__ void gate_kernel(const float* __restrict__ bih, const float* __restrict__ bhh,
                            const float* __restrict__ attw, int l, int first) {
    int n = blockIdx.x;
    int j = threadIdx.x;  // 192 threads
    size_t gb = (size_t)n * G4;
    float gi = g_G[gb + j]          + bih[j]          + bhh[j];
    float gf = g_G[gb + H2 + j]     + bih[H2 + j]     + bhh[H2 + j];
    float gg = g_G[gb + 2 * H2 + j] + bih[2 * H2 + j] + bhh[2 * H2 + j];
    float go = g_G[gb + 3 * H2 + j] + bih[3 * H2 + j] + bhh[3 * H2 + j];
    size_t hb = (size_t)n * H2 + j;
    float c = g_c[hb];
    c = sigm(gf) * c + sigm(gi) * tanhf(gg);
    float h = sigm(go) * tanhf(c);
    g_c[hb] = c;
    g_h[hb] = h;

    float part = h * attw[j];
#pragma unroll
    for (int o = 16; o; o >>= 1) part += __shfl_down_sync(0xffffffffu, part, o);
    __shared__ float ws[6];
    if ((j & 31) == 0) ws[j >> 5] = part;
    __syncthreads();
    if (j == 0) {
        float v = ws[0] + ws[1] + ws[2] + ws[3] + ws[4] + ws[5];
        if (first) g_s[l * NN + n] = v;
        else g_s[l * NN + n] += v;
    }
}

__global__ void jk_kernel(int br) {
    int idx = blockIdx.x * 256 + threadIdx.x;
    if (idx >= NN * HID) return;
    int n = idx >> 7;
    float s0 = g_s[n], s1 = g_s[NN + n], s2 = g_s[2 * NN + n];
    float m = fmaxf(s0, fmaxf(s1, s2));
    float e0 = expf(s0 - m), e1 = expf(s1 - m), e2 = expf(s2 - m);
    float inv = 1.f / (e0 + e1 + e2);
    g_jk[br][idx] = (e0 * g_xs[br][0][idx] + e1 * g_xs[br][1][idx] + e2 * g_xs[br][2][idx]) * inv;
}

__global__ void final_kernel(const float* __restrict__ lastW, float* __restrict__ out) {
    int n = blockIdx.x, c = threadIdx.x;  // 128 threads
    __shared__ float red[4][129];
    size_t base = (size_t)n * HID + c;
    float w = lastW[c];
    float o0 = g_outs[0][base], o1 = g_outs[1][base], o2 = g_outs[2][base], o3 = g_outs[3][base];
    red[0][c] = o0 * w; red[1][c] = o1 * w; red[2][c] = o2 * w; red[3][c] = o3 * w;
    __syncthreads();
    for (int st = 64; st > 0; st >>= 1) {
        if (c < st) {
            red[0][c] += red[0][c + st];
            red[1][c] += red[1][c + st];
            red[2][c] += red[2][c + st];
            red[3][c] += red[3][c + st];
        }
        __syncthreads();
    }
    float z0 = red[0][0], z1 = red[1][0], z2 = red[2][0], z3 = red[3][0];
    float m = fmaxf(fmaxf(z0, z1), fmaxf(z2, z3));
    float e0 = expf(z0 - m), e1 = expf(z1 - m), e2 = expf(z2 - m), e3 = expf(z3 - m);
    float inv = 1.f / (e0 + e1 + e2 + e3);
    out[base] = (e0 * o0 + e1 * o1 + e2 * o2 + e3 * o3) * inv;
}

// ------------------------- host orchestration -------------------------
static void gemm(const float* A, const float* B, const float* bias, float* C,
                 int M, int Nn, int K, bool transB, bool acc, bool useBias) {
    dim3 grid(Nn / 128, (M + 127) / 128);
    if (transB) {
        if (acc) sgemm_kernel<1, 1, 0><<<grid, 256>>>(A, B, bias, C, M, Nn, K);
        else     sgemm_kernel<1, 0, 0><<<grid, 256>>>(A, B, bias, C, M, Nn, K);
    } else {
        if (useBias) sgemm_kernel<0, 0, 1><<<grid, 256>>>(A, B, bias, C, M, Nn, K);
        else         sgemm_kernel<0, 0, 0><<<grid, 256>>>(A, B, bias, C, M, Nn, K);
    }
}

extern "C" void kernel_launch(void* const* d_in, const int* in_sizes, int n_in,
                              void* d_out, int out_size) {
    (void)in_sizes; (void)n_in; (void)out_size;
    const int*   x_idx    = (const int*)d_in[0];
    const float* x_flt    = (const float*)d_in[1];
    const int*   ei_l     = (const int*)d_in[2];
    const int*   ei_r     = (const int*)d_in[3];
    const float* emb_aa   = (const float*)d_in[4];
    const float* emb_ss   = (const float*)d_in[5];
    const float* conv_W   = (const float*)d_in[6];
    const float* c_asrc   = (const float*)d_in[7];
    const float* c_adst   = (const float*)d_in[8];
    const float* conv_b   = (const float*)d_in[9];
    const float* Wih      = (const float*)d_in[10];
    const float* Whh      = (const float*)d_in[11];
    const float* bih      = (const float*)d_in[12];
    const float* bhh      = (const float*)d_in[13];
    const float* jkW      = (const float*)d_in[14];
    /* d_in[15] jk_att_b: constant shift inside softmax over layers -> cancels */
    const float* dW       = (const float*)d_in[16];
    const float* dB       = (const float*)d_in[17];
    const float* fW       = (const float*)d_in[18];
    const float* fB       = (const float*)d_in[19];
    const float* lW       = (const float*)d_in[20];
    float* out = (float*)d_out;

    void* tp;
    float *p_x0, *p_xs, *p_xh, *p_G, *p_h, *p_jk, *p_sq, *p_outs;
    cudaGetSymbolAddress(&tp, g_x0);   p_x0   = (float*)tp;
    cudaGetSymbolAddress(&tp, g_xs);   p_xs   = (float*)tp;
    cudaGetSymbolAddress(&tp, g_xh);   p_xh   = (float*)tp;
    cudaGetSymbolAddress(&tp, g_G);    p_G    = (float*)tp;
    cudaGetSymbolAddress(&tp, g_h);    p_h    = (float*)tp;
    cudaGetSymbolAddress(&tp, g_jk);   p_jk   = (float*)tp;
    cudaGetSymbolAddress(&tp, g_sq);   p_sq   = (float*)tp;
    cudaGetSymbolAddress(&tp, g_outs); p_outs = (float*)tp;

    const size_t NH = (size_t)NN * HID;

    embed_kernel<<<(2 * NN * HID + 255) / 256, 256>>>(x_idx, x_flt, emb_aa, emb_ss);
    build_edges<<<(ET + 255) / 256, 256>>>(ei_l, ei_r);

    // ---- 3 GAT layers, 2 branches ----
    for (int layer = 0; layer < 3; layer++) {
        const float* xl = (layer == 0) ? p_x0           : p_xs + (size_t)(0 * 3 + layer - 1) * NH;
        const float* xr = (layer == 0) ? p_x0 + NH      : p_xs + (size_t)(1 * 3 + layer - 1) * NH;
        mean_kernel<<<(NN * HID + 255) / 256, 256>>>(xl, xr);
        for (int br = 0; br < 2; br++) {
            const float* x = br ? xr : xl;
            int li = br * 3 + layer;
            gemm(x, conv_W + (size_t)li * HID * 256, nullptr, p_xh, NN, 256, HID, false, false, false);
            att_kernel<<<NN, 256>>>(c_asrc + (size_t)li * 256, c_adst + (size_t)li * 256);
            clear_conv<<<(NN * 256 + 255) / 256, 256>>>();
            edge_passA<<<(ET + 255) / 256, 256>>>(br);
            edge_passB<<<(ET + 255) / 256, 256>>>(br);
            edge_passC<<<(ET + 3) / 4, 256>>>(br);
            finalize_conv<<<(NN * HID + 255) / 256, 256>>>(br, layer, conv_b + (size_t)li * HID);
        }
    }

    // ---- JK bi-LSTM per branch ----
    for (int br = 0; br < 2; br++) {
        for (int dir = 0; dir < 2; dir++) {
            clear_hc<<<(NN * H2 + 255) / 256, 256>>>();
            const float* wih = Wih + (size_t)(br * 2 + dir) * G4 * HID;
            const float* whh = Whh + (size_t)(br * 2 + dir) * G4 * H2;
            const float* bi  = bih + (size_t)(br * 2 + dir) * G4;
            const float* bh  = bhh + (size_t)(br * 2 + dir) * G4;
            const float* aw  = jkW + (size_t)br * (2 * H2) + (size_t)dir * H2;
            for (int st = 0; st < 3; st++) {
                int l = dir ? (2 - st) : st;
                gemm(p_xs + (size_t)(br * 3 + l) * NH, wih, nullptr, p_G, NN, G4, HID, true, false, false);
                gemm(p_h, whh, nullptr, p_G, NN, G4, H2, true, true, false);
                gate_kernel<<<NN, H2>>>(bi, bh, aw, l, dir == 0 ? 1 : 0);
            }
        }
        jk_kernel<<<(NN * HID + 255) / 256, 256>>>(br);
        gemm(p_jk + (size_t)br * NH, dW + (size_t)br * HID * HID, dB + (size_t)br * HID,
             p_sq + (size_t)br * NH, NN, HID, HID, false, false, true);
    }

    // ---- final projections + attention mix ----
    const float* featA[4] = { p_jk, p_sq, p_jk + NH, p_sq + NH };
    for (int i = 0; i < 4; i++) {
        gemm(featA[i], fW + (size_t)i * HID * HID, fB + (size_t)i * HID,
             p_outs + (size_t)i * NH, NN, HID, HID, false, false, true);
    }
    final_kernel<<<NN, HID>>>(lW, out);
}

// round 5
// speedup vs baseline: 1.6672x; 1.6672x over previous
#include <cuda_runtime.h>
#include <math.h>

#define NN 100000
#define EE 800000
#define ET (EE + NN)
#define HID 128
#define H2 192
#define G4 768

// ------------------------- scratch (static device globals) -------------------------
__device__ float g_x0[2][NN * HID];          // initial embeddings per branch
__device__ float g_xs[2][3][NN * HID];       // per-layer conv outputs per branch
__device__ float g_mean[NN * HID];           // 0.5*(x_l + x_r) of layer inputs
__device__ float g_xh[NN * 256];             // x @ W   [N, heads*hid]
__device__ float g_gat[NN * 256];            // scatter accumulator [N, heads, hid]
__device__ float g_asrc[NN * 2];
__device__ float g_adst[NN * 2];
__device__ unsigned g_mmax[NN * 2];          // encoded segment max
__device__ float g_den[NN * 2];              // segment softmax denominator
__device__ int g_src[2][ET];
__device__ int g_dst[2][ET];
__device__ float g_eval[ET * 2];             // edge logits -> exp values
__device__ float g_G[(size_t)NN * G4];       // LSTM gate pre-activations
__device__ float g_h[NN * H2];
__device__ float g_c[NN * H2];
__device__ float g_s[3 * NN];                // JK attention logits
__device__ float g_jk[2][NN * HID];
__device__ float g_sq[2][NN * HID];
__device__ float g_outs[4][NN * HID];

__device__ __forceinline__ float sigm(float x) { return 1.0f / (1.0f + expf(-x)); }

__device__ __forceinline__ unsigned f2tf(float f) {
    unsigned r;
    asm("cvt.rna.tf32.f32 %0, %1;" : "=r"(r) : "f"(f));
    return r;
}

__device__ __forceinline__ void mma_tf32(float* d, const unsigned* a, const unsigned* b) {
    asm volatile(
        "mma.sync.aligned.m16n8k8.row.col.f32.tf32.tf32.f32 "
        "{%0,%1,%2,%3}, {%4,%5,%6,%7}, {%8,%9}, {%0,%1,%2,%3};\n"
        : "+f"(d[0]), "+f"(d[1]), "+f"(d[2]), "+f"(d[3])
        : "r"(a[0]), "r"(a[1]), "r"(a[2]), "r"(a[3]), "r"(b[0]), "r"(b[1]));
}

// ------------------------- TF32 tensor-core GEMM: 128x128 block, 8 warps -------------------------
// C[M,Nn] = A[M,K] * op(B) (+ bias) (+ C).  TRANSB: B is [Nn,K] row-major.
// Requires K%32==0, Nn%128==0 (call sites: K in {128,192}, Nn in {128,256,768}).
template <int TRANSB, int ACC, int BIAS>
__global__ __launch_bounds__(256) void tgemm_kernel(
    const float* __restrict__ A, const float* __restrict__ B,
    const float* __restrict__ bias, float* __restrict__ C,
    int M, int Nn, int K) {
    __shared__ unsigned As[128][36];   // [m][k], pad 36 -> frag LDS conflict-free
    __shared__ unsigned Bs[32][136];   // [k][n], pad 136 -> frag LDS conflict-free
    int tid = threadIdx.x;
    int lane = tid & 31, wid = tid >> 5;
    int wm = wid & 3, wn = wid >> 2;        // 4x2 warp grid; warp tile 32m x 64n
    int grp = lane >> 2, tg = lane & 3;
    int bm = blockIdx.y * 128, bn = blockIdx.x * 128;

    float cf[2][8][4] = {};                  // [mtile][ntile][reg]

    const int arow = tid >> 1;               // 0..127
    const int akoff = (tid & 1) * 16;        // 0 / 16

    for (int k0 = 0; k0 < K; k0 += 32) {
        // ---- A tile: 128 x 32 ----
        {
            int gm = bm + arow;
#pragma unroll
            for (int i = 0; i < 4; i++) {
                float4 v = make_float4(0.f, 0.f, 0.f, 0.f);
                if (gm < M) v = *(const float4*)(A + (size_t)gm * K + k0 + akoff + 4 * i);
                uint4 u = make_uint4(f2tf(v.x), f2tf(v.y), f2tf(v.z), f2tf(v.w));
                *(uint4*)&As[arow][akoff + 4 * i] = u;
            }
        }
        // ---- B tile -> Bs[k][n] 32 x 128 ----
        if (!TRANSB) {
            int brow = tid >> 3;             // 0..31 (k)
            int bnoff = (tid & 7) * 16;      // n
#pragma unroll
            for (int i = 0; i < 4; i++) {
                float4 v = *(const float4*)(B + (size_t)(k0 + brow) * Nn + bn + bnoff + 4 * i);
                uint4 u = make_uint4(f2tf(v.x), f2tf(v.y), f2tf(v.z), f2tf(v.w));
                *(uint4*)&Bs[brow][bnoff + 4 * i] = u;
            }
        } else {
            int bnrow = tid >> 1;            // 0..127 (n)
            int bkoff = (tid & 1) * 16;      // k
#pragma unroll
            for (int i = 0; i < 4; i++) {
                float4 v = *(const float4*)(B + (size_t)(bn + bnrow) * K + k0 + bkoff + 4 * i);
                Bs[bkoff + 4 * i + 0][bnrow] = f2tf(v.x);
                Bs[bkoff + 4 * i + 1][bnrow] = f2tf(v.y);
                Bs[bkoff + 4 * i + 2][bnrow] = f2tf(v.z);
                Bs[bkoff + 4 * i + 3][bnrow] = f2tf(v.w);
            }
        }
        __syncthreads();

#pragma unroll
        for (int ks = 0; ks < 32; ks += 8) {
            unsigned af[2][4];
#pragma unroll
            for (int mt = 0; mt < 2; mt++) {
                int m0 = wm * 32 + mt * 16;
                af[mt][0] = As[m0 + grp][ks + tg];
                af[mt][1] = As[m0 + grp + 8][ks + tg];
                af[mt][2] = As[m0 + grp][ks + tg + 4];
                af[mt][3] = As[m0 + grp + 8][ks + tg + 4];
            }
#pragma unroll
            for (int nt = 0; nt < 8; nt++) {
                unsigned bf[2];
                int n0 = wn * 64 + nt * 8;
                bf[0] = Bs[ks + tg][n0 + grp];
                bf[1] = Bs[ks + tg + 4][n0 + grp];
#pragma unroll
                for (int mt = 0; mt < 2; mt++)
                    mma_tf32(cf[mt][nt], af[mt], bf);
            }
        }
        __syncthreads();
    }

    // ---- epilogue ----
#pragma unroll
    for (int mt = 0; mt < 2; mt++) {
        int row0 = bm + wm * 32 + mt * 16 + grp;
#pragma unroll
        for (int nt = 0; nt < 8; nt++) {
            int col = bn + wn * 64 + nt * 8 + 2 * tg;
            float b0 = 0.f, b1 = 0.f;
            if (BIAS) { b0 = bias[col]; b1 = bias[col + 1]; }
            if (row0 < M) {
                float2* p = (float2*)(C + (size_t)row0 * Nn + col);
                float2 v = make_float2(cf[mt][nt][0] + b0, cf[mt][nt][1] + b1);
                if (ACC) { float2 o = *p; v.x += o.x; v.y += o.y; }
                *p = v;
            }
            int row1 = row0 + 8;
            if (row1 < M) {
                float2* p = (float2*)(C + (size_t)row1 * Nn + col);
                float2 v = make_float2(cf[mt][nt][2] + b0, cf[mt][nt][3] + b1);
                if (ACC) { float2 o = *p; v.x += o.x; v.y += o.y; }
                *p = v;
            }
        }
    }
}

// ------------------------- pointwise / graph kernels -------------------------
__global__ void embed_kernel(const int* __restrict__ x_idx, const float* __restrict__ x_flt,
                             const float* __restrict__ emb_aa, const float* __restrict__ emb_ss) {
    int idx = blockIdx.x * 256 + threadIdx.x;
    if (idx >= 2 * NN * HID) return;
    int br = idx / (NN * HID);
    int r = idx - br * (NN * HID);
    int n = r >> 7, c = r & 127;
    float v;
    if (c < 123) {
        int ai = x_idx[n * 2], si = x_idx[n * 2 + 1];
        v = emb_aa[((size_t)br * 26 + ai) * 123 + c] + emb_ss[((size_t)br * 3 + si) * 123 + c];
    } else {
        v = x_flt[n * 5 + (c - 123)];
    }
    g_x0[br][r] = v;
}

__global__ void build_edges(const int* __restrict__ el, const int* __restrict__ er) {
    int i = blockIdx.x * 256 + threadIdx.x;
    if (i >= ET) return;
    int sl, dl, sr, dr;
    if (i < EE) { sl = el[i]; dl = el[EE + i]; sr = er[i]; dr = er[EE + i]; }
    else { sl = dl = sr = dr = i - EE; }
    g_src[0][i] = sl; g_dst[0][i] = dl;
    g_src[1][i] = sr; g_dst[1][i] = dr;
}

__global__ void mean_kernel(const float* __restrict__ xl, const float* __restrict__ xr) {
    int idx = blockIdx.x * 256 + threadIdx.x;
    if (idx >= NN * HID) return;
    g_mean[idx] = 0.5f * (xl[idx] + xr[idx]);
}

__global__ void att_kernel(const float* __restrict__ aw_src, const float* __restrict__ aw_dst) {
    int n = blockIdx.x, t = threadIdx.x;
    __shared__ float rs[256], rd[256];
    float v = g_xh[(size_t)n * 256 + t];
    rs[t] = v * aw_src[t];
    rd[t] = v * aw_dst[t];
    __syncthreads();
    int h = t >> 7, c = t & 127;
    for (int st = 64; st > 0; st >>= 1) {
        if (c < st) { rs[t] += rs[t + st]; rd[t] += rd[t + st]; }
        __syncthreads();
    }
    if (c == 0) { g_asrc[n * 2 + h] = rs[t]; g_adst[n * 2 + h] = rd[t]; }
}

__global__ void clear_conv() {
    int idx = blockIdx.x * 256 + threadIdx.x;
    if (idx < NN * 256) g_gat[idx] = 0.f;
    if (idx < NN * 2) { g_mmax[idx] = 0u; g_den[idx] = 0.f; }
}

__device__ __forceinline__ unsigned enc_f(float v) {
    unsigned u = __float_as_uint(v);
    return (u & 0x80000000u) ? ~u : (u | 0x80000000u);
}
__device__ __forceinline__ float dec_f(unsigned e) {
    unsigned u = (e & 0x80000000u) ? (e ^ 0x80000000u) : ~e;
    return __uint_as_float(u);
}

__global__ void edge_passA(int br) {
    int e = blockIdx.x * 256 + threadIdx.x;
    if (e >= ET) return;
    int s = g_src[br][e], d = g_dst[br][e];
#pragma unroll
    for (int h = 0; h < 2; h++) {
        float v = g_asrc[s * 2 + h] + g_adst[d * 2 + h];
        v = v > 0.f ? v : 0.2f * v;   // leaky_relu(0.2)
        g_eval[e * 2 + h] = v;
        atomicMax(&g_mmax[d * 2 + h], enc_f(v));
    }
}

__global__ void edge_passB(int br) {
    int e = blockIdx.x * 256 + threadIdx.x;
    if (e >= ET) return;
    int d = g_dst[br][e];
#pragma unroll
    for (int h = 0; h < 2; h++) {
        float m = dec_f(g_mmax[d * 2 + h]);
        float ex = expf(g_eval[e * 2 + h] - m);
        g_eval[e * 2 + h] = ex;
        atomicAdd(&g_den[d * 2 + h], ex);
    }
}

// 4 edges per block: 256 threads each sweep full 256-channel row per edge.
__global__ __launch_bounds__(256) void edge_passC(int br) {
    int t = threadIdx.x;
    int h = t >> 7;
    int e0 = blockIdx.x * 4;
#pragma unroll
    for (int sub = 0; sub < 4; sub++) {
        int e = e0 + sub;
        if (e >= ET) return;
        int s = g_src[br][e], d = g_dst[br][e];
        float alpha = g_eval[e * 2 + h] / (g_den[d * 2 + h] + 1e-16f);
        atomicAdd(&g_gat[(size_t)d * 256 + t], g_xh[(size_t)s * 256 + t] * alpha);
    }
}

__global__ void finalize_conv(int br, int layer, const float* __restrict__ bias) {
    int idx = blockIdx.x * 256 + threadIdx.x;
    if (idx >= NN * HID) return;
    int n = idx >> 7, c = idx & 127;
    float gm = 0.5f * (g_gat[(size_t)n * 256 + c] + g_gat[(size_t)n * 256 + 128 + c]) + bias[c];
    g_xs[br][layer][idx] = g_mean[idx] + fmaxf(gm, 0.f);
}

__global__ void clear_hc() {
    int idx = blockIdx.x * 256 + threadIdx.x;
    if (idx >= NN * H2) return;
    g_h[idx] = 0.f;
    g_c[idx] = 0.f;
}

__global__ void gate_kernel(const float* __restrict__ bih, const float* __restrict__ bhh,
                            const float* __restrict__ attw, int l, int first) {
    int n = blockIdx.x;
    int j = threadIdx.x;  // 192 threads
    size_t gb = (size_t)n * G4;
    float gi = g_G[gb + j]          + bih[j]          + bhh[j];
    float gf = g_G[gb + H2 + j]     + bih[H2 + j]     + bhh[H2 + j];
    float gg = g_G[gb + 2 * H2 + j] + bih[2 * H2 + j] + bhh[2 * H2 + j];
    float go = g_G[gb + 3 * H2 + j] + bih[3 * H2 + j] + bhh[3 * H2 + j];
    size_t hb = (size_t)n * H2 + j;
    float c = g_c[hb];
    c = sigm(gf) * c + sigm(gi) * tanhf(gg);
    float h = sigm(go) * tanhf(c);
    g_c[hb] = c;
    g_h[hb] = h;

    float part = h * attw[j];
#pragma unroll
    for (int o = 16; o; o >>= 1) part += __shfl_down_sync(0xffffffffu, part, o);
    __shared__ float ws[6];
    if ((j & 31) == 0) ws[j >> 5] = part;
    __syncthreads();
    if (j == 0) {
        float v = ws[0] + ws[1] + ws[2] + ws[3] + ws[4] + ws[5];
        if (first) g_s[l * NN + n] = v;
        else g_s[l * NN + n] += v;
    }
}

__global__ void jk_kernel(int br) {
    int idx = blockIdx.x * 256 + threadIdx.x;
    if (idx >= NN * HID) return;
    int n = idx >> 7;
    float s0 = g_s[n], s1 = g_s[NN + n], s2 = g_s[2 * NN + n];
    float m = fmaxf(s0, fmaxf(s1, s2));
    float e0 = expf(s0 - m), e1 = expf(s1 - m), e2 = expf(s2 - m);
    float inv = 1.f / (e0 + e1 + e2);
    g_jk[br][idx] = (e0 * g_xs[br][0][idx] + e1 * g_xs[br][1][idx] + e2 * g_xs[br][2][idx]) * inv;
}

__global__ void final_kernel(const float* __restrict__ lastW, float* __restrict__ out) {
    int n = blockIdx.x, c = threadIdx.x;  // 128 threads
    __shared__ float red[4][129];
    size_t base = (size_t)n * HID + c;
    float w = lastW[c];
    float o0 = g_outs[0][base], o1 = g_outs[1][base], o2 = g_outs[2][base], o3 = g_outs[3][base];
    red[0][c] = o0 * w; red[1][c] = o1 * w; red[2][c] = o2 * w; red[3][c] = o3 * w;
    __syncthreads();
    for (int st = 64; st > 0; st >>= 1) {
        if (c < st) {
            red[0][c] += red[0][c + st];
            red[1][c] += red[1][c + st];
            red[2][c] += red[2][c + st];
            red[3][c] += red[3][c + st];
        }
        __syncthreads();
    }
    float z0 = red[0][0], z1 = red[1][0], z2 = red[2][0], z3 = red[3][0];
    float m = fmaxf(fmaxf(z0, z1), fmaxf(z2, z3));
    float e0 = expf(z0 - m), e1 = expf(z1 - m), e2 = expf(z2 - m), e3 = expf(z3 - m);
    float inv = 1.f / (e0 + e1 + e2 + e3);
    out[base] = (e0 * o0 + e1 * o1 + e2 * o2 + e3 * o3) * inv;
}

// ------------------------- host orchestration -------------------------
static void gemm(const float* A, const float* B, const float* bias, float* C,
                 int M, int Nn, int K, bool transB, bool acc, bool useBias) {
    dim3 grid(Nn / 128, (M + 127) / 128);
    if (transB) {
        if (acc) tgemm_kernel<1, 1, 0><<<grid, 256>>>(A, B, bias, C, M, Nn, K);
        else     tgemm_kernel<1, 0, 0><<<grid, 256>>>(A, B, bias, C, M, Nn, K);
    } else {
        if (useBias) tgemm_kernel<0, 0, 1><<<grid, 256>>>(A, B, bias, C, M, Nn, K);
        else         tgemm_kernel<0, 0, 0><<<grid, 256>>>(A, B, bias, C, M, Nn, K);
    }
}

extern "C" void kernel_launch(void* const* d_in, const int* in_sizes, int n_in,
                              void* d_out, int out_size) {
    (void)in_sizes; (void)n_in; (void)out_size;
    const int*   x_idx    = (const int*)d_in[0];
    const float* x_flt    = (const float*)d_in[1];
    const int*   ei_l     = (const int*)d_in[2];
    const int*   ei_r     = (const int*)d_in[3];
    const float* emb_aa   = (const float*)d_in[4];
    const float* emb_ss   = (const float*)d_in[5];
    const float* conv_W   = (const float*)d_in[6];
    const float* c_asrc   = (const float*)d_in[7];
    const float* c_adst   = (const float*)d_in[8];
    const float* conv_b   = (const float*)d_in[9];
    const float* Wih      = (const float*)d_in[10];
    const float* Whh      = (const float*)d_in[11];
    const float* bih      = (const float*)d_in[12];
    const float* bhh      = (const float*)d_in[13];
    const float* jkW      = (const float*)d_in[14];
    /* d_in[15] jk_att_b: constant shift inside softmax over layers -> cancels */
    const float* dW       = (const float*)d_in[16];
    const float* dB       = (const float*)d_in[17];
    const float* fW       = (const float*)d_in[18];
    const float* fB       = (const float*)d_in[19];
    const float* lW       = (const float*)d_in[20];
    float* out = (float*)d_out;

    void* tp;
    float *p_x0, *p_xs, *p_xh, *p_G, *p_h, *p_jk, *p_sq, *p_outs;
    cudaGetSymbolAddress(&tp, g_x0);   p_x0   = (float*)tp;
    cudaGetSymbolAddress(&tp, g_xs);   p_xs   = (float*)tp;
    cudaGetSymbolAddress(&tp, g_xh);   p_xh   = (float*)tp;
    cudaGetSymbolAddress(&tp, g_G);    p_G    = (float*)tp;
    cudaGetSymbolAddress(&tp, g_h);    p_h    = (float*)tp;
    cudaGetSymbolAddress(&tp, g_jk);   p_jk   = (float*)tp;
    cudaGetSymbolAddress(&tp, g_sq);   p_sq   = (float*)tp;
    cudaGetSymbolAddress(&tp, g_outs); p_outs = (float*)tp;

    const size_t NH = (size_t)NN * HID;

    embed_kernel<<<(2 * NN * HID + 255) / 256, 256>>>(x_idx, x_flt, emb_aa, emb_ss);
    build_edges<<<(ET + 255) / 256, 256>>>(ei_l, ei_r);

    // ---- 3 GAT layers, 2 branches ----
    for (int layer = 0; layer < 3; layer++) {
        const float* xl = (layer == 0) ? p_x0           : p_xs + (size_t)(0 * 3 + layer - 1) * NH;
        const float* xr = (layer == 0) ? p_x0 + NH      : p_xs + (size_t)(1 * 3 + layer - 1) * NH;
        mean_kernel<<<(NN * HID + 255) / 256, 256>>>(xl, xr);
        for (int br = 0; br < 2; br++) {
            const float* x = br ? xr : xl;
            int li = br * 3 + layer;
            gemm(x, conv_W + (size_t)li * HID * 256, nullptr, p_xh, NN, 256, HID, false, false, false);
            att_kernel<<<NN, 256>>>(c_asrc + (size_t)li * 256, c_adst + (size_t)li * 256);
            clear_conv<<<(NN * 256 + 255) / 256, 256>>>();
            edge_passA<<<(ET + 255) / 256, 256>>>(br);
            edge_passB<<<(ET + 255) / 256, 256>>>(br);
            edge_passC<<<(ET + 3) / 4, 256>>>(br);
            finalize_conv<<<(NN * HID + 255) / 256, 256>>>(br, layer, conv_b + (size_t)li * HID);
        }
    }

    // ---- JK bi-LSTM per branch ----
    for (int br = 0; br < 2; br++) {
        for (int dir = 0; dir < 2; dir++) {
            clear_hc<<<(NN * H2 + 255) / 256, 256>>>();
            const float* wih = Wih + (size_t)(br * 2 + dir) * G4 * HID;
            const float* whh = Whh + (size_t)(br * 2 + dir) * G4 * H2;
            const float* bi  = bih + (size_t)(br * 2 + dir) * G4;
            const float* bh  = bhh + (size_t)(br * 2 + dir) * G4;
            const float* aw  = jkW + (size_t)br * (2 * H2) + (size_t)dir * H2;
            for (int st = 0; st < 3; st++) {
                int l = dir ? (2 - st) : st;
                gemm(p_xs + (size_t)(br * 3 + l) * NH, wih, nullptr, p_G, NN, G4, HID, true, false, false);
                gemm(p_h, whh, nullptr, p_G, NN, G4, H2, true, true, false);
                gate_kernel<<<NN, H2>>>(bi, bh, aw, l, dir == 0 ? 1 : 0);
            }
        }
        jk_kernel<<<(NN * HID + 255) / 256, 256>>>(br);
        gemm(p_jk + (size_t)br * NH, dW + (size_t)br * HID * HID, dB + (size_t)br * HID,
             p_sq + (size_t)br * NH, NN, HID, HID, false, false, true);
    }

    // ---- final projections + attention mix ----
    const float* featA[4] = { p_jk, p_sq, p_jk + NH, p_sq + NH };
    for (int i = 0; i < 4; i++) {
        gemm(featA[i], fW + (size_t)i * HID * HID, fB + (size_t)i * HID,
             p_outs + (size_t)i * NH, NN, HID, HID, false, false, true);
    }
    final_kernel<<<NN, HID>>>(lW, out);
}

// round 11
// speedup vs baseline: 2.0511x; 1.2303x over previous
#include <cuda_runtime.h>
#include <math.h>
#include <stdint.h>

#define NN 100000
#define EE 800000
#define ET (EE + NN)
#define HID 128
#define H2 192
#define G4 768

// ------------------------- scratch (static device globals) -------------------------
__device__ float g_x0[2][NN * HID];
__device__ float g_xs[2][3][NN * HID];
__device__ float g_mean[NN * HID];
__device__ float g_xh[NN * 256];
__device__ float g_gat[NN * 256];
__device__ float g_asrc[NN * 2];
__device__ float g_adst[NN * 2];
__device__ unsigned g_mmax[NN * 2];
__device__ float g_den[NN * 2];
__device__ int g_src[2][ET];
__device__ int g_dst[2][ET];
__device__ float g_eval[ET * 2];
__device__ float g_G[(size_t)NN * G4];
__device__ float g_h[NN * H2];
__device__ float g_c[NN * H2];
__device__ float g_s[3 * NN];
__device__ float g_jk[2][NN * HID];
__device__ float g_sq[2][NN * HID];
__device__ float g_outs[4][NN * HID];

// tf32 shadow copies (A operands of GEMMs)
__device__ unsigned g_x0tf[2][NN * HID];
__device__ unsigned g_xstf[2][3][NN * HID];
__device__ unsigned g_htf[NN * H2];
__device__ unsigned g_jktf[2][NN * HID];
__device__ unsigned g_sqtf[2][NN * HID];

// tf32 weights, packed
#define OFF_CONV 0
#define SZ_CONV  (6 * 128 * 256)
#define OFF_WIH  (OFF_CONV + SZ_CONV)
#define SZ_WIH   (4 * G4 * HID)
#define OFF_WHH  (OFF_WIH + SZ_WIH)
#define SZ_WHH   (4 * G4 * H2)
#define OFF_DW   (OFF_WHH + SZ_WHH)
#define SZ_DW    (2 * HID * HID)
#define OFF_FW   (OFF_DW + SZ_DW)
#define SZ_FW    (4 * HID * HID)
__device__ unsigned g_Wtf[OFF_FW + SZ_FW];

// CSR scratch
__device__ int g_cnt[2][NN];
__device__ int g_row[2][NN + 1];
__device__ int g_cur[2][NN];
__device__ int g_bsum[2][128];
__device__ int g_csr_src[2][ET];
__device__ int g_csr_eid[2][ET];

__device__ __forceinline__ float sigm(float x) { return 1.0f / (1.0f + expf(-x)); }

__device__ __forceinline__ unsigned f2tf(float f) {
    unsigned r;
    asm("cvt.rna.tf32.f32 %0, %1;" : "=r"(r) : "f"(f));
    return r;
}

__device__ __forceinline__ void mma_tf32(float* d, const unsigned* a, const unsigned* b) {
    asm volatile(
        "mma.sync.aligned.m16n8k8.row.col.f32.tf32.tf32.f32 "
        "{%0,%1,%2,%3}, {%4,%5,%6,%7}, {%8,%9}, {%0,%1,%2,%3};\n"
        : "+f"(d[0]), "+f"(d[1]), "+f"(d[2]), "+f"(d[3])
        : "r"(a[0]), "r"(a[1]), "r"(a[2]), "r"(a[3]), "r"(b[0]), "r"(b[1]));
}

__device__ __forceinline__ void cpa16(uint32_t dst, const void* src, int srcbytes) {
    asm volatile("cp.async.ca.shared.global [%0], [%1], 16, %2;\n"
                 :: "r"(dst), "l"(src), "r"(srcbytes));
}
#define CPA_COMMIT() asm volatile("cp.async.commit_group;\n" ::: "memory")
#define CPA_WAIT1()  asm volatile("cp.async.wait_group 1;\n" ::: "memory")
#define CPA_WAIT0()  asm volatile("cp.async.wait_group 0;\n" ::: "memory")

// ------------------------- TF32 GEMM, cp.async double-buffered -------------------------
// C[M,Nn] = A[M,K] * op(B) (+ bias) (+ C).  A,B pre-converted tf32 (u32).
// TRANSB: B is [Nn,K] row-major.  K%32==0, Nn%128==0.
// Stage layout (words): A tile 128x32 pitch 36 (4608), B tile 4608 region.
#define STG_WORDS 9216
#define GEMM_SMEM (2 * STG_WORDS * 4)

template <int TRANSB, int ACC, int BIAS, int WTF>
__global__ __launch_bounds__(256) void tgemm2(
    const unsigned* __restrict__ A, const unsigned* __restrict__ B,
    const float* __restrict__ bias, float* __restrict__ C,
    unsigned* __restrict__ Ctf, int M, int Nn, int K) {
    extern __shared__ unsigned smem[];
    uint32_t sb;
    asm("{ .reg .u64 t; cvta.to.shared.u64 t, %1; cvt.u32.u64 %0, t; }"
        : "=r"(sb) : "l"(smem));

    int tid = threadIdx.x;
    int lane = tid & 31, wid = tid >> 5;
    int wm = wid & 3, wn = wid >> 2;
    int grp = lane >> 2, tg = lane & 3;
    int bm = blockIdx.y * 128, bn = blockIdx.x * 128;

    float cf[2][8][4] = {};

    const int arow = tid >> 1, akoff = (tid & 1) * 16;
    const int gm_a = bm + arow;
    const int apred = (gm_a < M) ? 16 : 0;
    int nk = K / 32;

    // stage loader
    auto load_stage = [&](int stg, int k0) {
        uint32_t base = sb + (uint32_t)stg * (STG_WORDS * 4);
        {   // A 128x32
            const unsigned* src = A + (size_t)gm_a * K + k0 + akoff;
            uint32_t dst = base + (uint32_t)(arow * 36 + akoff) * 4;
#pragma unroll
            for (int i = 0; i < 4; i++) cpa16(dst + 16 * i, src + 4 * i, apred);
        }
        if (!TRANSB) {  // B [K,Nn] -> Bs[k][n] 32x128 pitch 136
            int br_ = tid >> 3, bo = (tid & 7) * 16;
            const unsigned* src = B + (size_t)(k0 + br_) * Nn + bn + bo;
            uint32_t dst = base + (uint32_t)(4608 + br_ * 136 + bo) * 4;
#pragma unroll
            for (int i = 0; i < 4; i++) cpa16(dst + 16 * i, src + 4 * i, 16);
        } else {        // B [Nn,K] -> Bs2[n][k] 128x32 pitch 36
            int br_ = tid >> 1, bo = (tid & 1) * 16;
            const unsigned* src = B + (size_t)(bn + br_) * K + k0 + bo;
            uint32_t dst = base + (uint32_t)(4608 + br_ * 36 + bo) * 4;
#pragma unroll
            for (int i = 0; i < 4; i++) cpa16(dst + 16 * i, src + 4 * i, 16);
        }
    };

    load_stage(0, 0);
    CPA_COMMIT();

    for (int i = 0; i < nk; i++) {
        if (i + 1 < nk) {
            load_stage((i + 1) & 1, (i + 1) * 32);
            CPA_COMMIT();
            CPA_WAIT1();
        } else {
            CPA_WAIT0();
        }
        __syncthreads();

        const unsigned* As = smem + (i & 1) * STG_WORDS;
        const unsigned* Bs = As + 4608;

#pragma unroll
        for (int ks = 0; ks < 32; ks += 8) {
            unsigned af[2][4];
#pragma unroll
            for (int mt = 0; mt < 2; mt++) {
                int m0 = wm * 32 + mt * 16;
                af[mt][0] = As[(m0 + grp) * 36 + ks + tg];
                af[mt][1] = As[(m0 + grp + 8) * 36 + ks + tg];
                af[mt][2] = As[(m0 + grp) * 36 + ks + tg + 4];
                af[mt][3] = As[(m0 + grp + 8) * 36 + ks + tg + 4];
            }
#pragma unroll
            for (int nt = 0; nt < 8; nt++) {
                unsigned bf[2];
                int n0 = wn * 64 + nt * 8;
                if (!TRANSB) {
                    bf[0] = Bs[(ks + tg) * 136 + n0 + grp];
                    bf[1] = Bs[(ks + tg + 4) * 136 + n0 + grp];
                } else {
                    bf[0] = Bs[(n0 + grp) * 36 + ks + tg];
                    bf[1] = Bs[(n0 + grp) * 36 + ks + tg + 4];
                }
#pragma unroll
                for (int mt = 0; mt < 2; mt++)
                    mma_tf32(cf[mt][nt], af[mt], bf);
            }
        }
        __syncthreads();
    }

    // ---- epilogue ----
#pragma unroll
    for (int mt = 0; mt < 2; mt++) {
        int row0 = bm + wm * 32 + mt * 16 + grp;
#pragma unroll
        for (int nt = 0; nt < 8; nt++) {
            int col = bn + wn * 64 + nt * 8 + 2 * tg;
            float b0 = 0.f, b1 = 0.f;
            if (BIAS) { b0 = bias[col]; b1 = bias[col + 1]; }
            if (row0 < M) {
                float2* p = (float2*)(C + (size_t)row0 * Nn + col);
                float2 v = make_float2(cf[mt][nt][0] + b0, cf[mt][nt][1] + b1);
                if (ACC) { float2 o = *p; v.x += o.x; v.y += o.y; }
                *p = v;
                if (WTF) {
                    Ctf[(size_t)row0 * Nn + col] = f2tf(v.x);
                    Ctf[(size_t)row0 * Nn + col + 1] = f2tf(v.y);
                }
            }
            int row1 = row0 + 8;
            if (row1 < M) {
                float2* p = (float2*)(C + (size_t)row1 * Nn + col);
                float2 v = make_float2(cf[mt][nt][2] + b0, cf[mt][nt][3] + b1);
                if (ACC) { float2 o = *p; v.x += o.x; v.y += o.y; }
                *p = v;
                if (WTF) {
                    Ctf[(size_t)row1 * Nn + col] = f2tf(v.x);
                    Ctf[(size_t)row1 * Nn + col + 1] = f2tf(v.y);
                }
            }
        }
    }
}

// ------------------------- weight conversion -------------------------
__global__ void conv_tf_kernel(const float* __restrict__ s, unsigned* __restrict__ d, int n) {
    int i = blockIdx.x * 256 + threadIdx.x;
    if (i < n) d[i] = f2tf(s[i]);
}

// ------------------------- pointwise / graph kernels -------------------------
// embed: also writes layer-0 mean (br==1 half recomputes br0 value; tables are L1/L2-resident)
__global__ void embed_kernel(const int* __restrict__ x_idx, const float* __restrict__ x_flt,
                             const float* __restrict__ emb_aa, const float* __restrict__ emb_ss) {
    int idx = blockIdx.x * 256 + threadIdx.x;
    if (idx >= 2 * NN * HID) return;
    int br = idx / (NN * HID);
    int r = idx - br * (NN * HID);
    int n = r >> 7, c = r & 127;
    float v;
    if (c < 123) {
        int ai = x_idx[n * 2], si = x_idx[n * 2 + 1];
        v = emb_aa[((size_t)br * 26 + ai) * 123 + c] + emb_ss[((size_t)br * 3 + si) * 123 + c];
        if (br == 1) {
            float v0 = emb_aa[(size_t)ai * 123 + c] + emb_ss[(size_t)si * 123 + c];
            g_mean[r] = 0.5f * (v0 + v);
        }
    } else {
        v = x_flt[n * 5 + (c - 123)];
        if (br == 1) g_mean[r] = v;   // both branches share x_flt columns
    }
    g_x0[br][r] = v;
    g_x0tf[br][r] = f2tf(v);
}

__global__ void zero_cnt() {
    int i = blockIdx.x * 256 + threadIdx.x;
    if (i < 2 * NN) ((int*)g_cnt)[i] = 0;
}

__global__ void build_edges(const int* __restrict__ el, const int* __restrict__ er) {
    int i = blockIdx.x * 256 + threadIdx.x;
    if (i >= ET) return;
    int sl, dl, sr, dr;
    if (i < EE) { sl = el[i]; dl = el[EE + i]; sr = er[i]; dr = er[EE + i]; }
    else { sl = dl = sr = dr = i - EE; }
    g_src[0][i] = sl; g_dst[0][i] = dl;
    g_src[1][i] = sr; g_dst[1][i] = dr;
    atomicAdd(&g_cnt[0][dl], 1);
    atomicAdd(&g_cnt[1][dr], 1);
}

__global__ void scan1() {
    int br = blockIdx.y;
    int t = threadIdx.x;
    int i = blockIdx.x * 1024 + t;
    int v = (i < NN) ? g_cnt[br][i] : 0;
    __shared__ int s[1024];
    s[t] = v;
    __syncthreads();
    for (int off = 1; off < 1024; off <<= 1) {
        int x = (t >= off) ? s[t - off] : 0;
        __syncthreads();
        s[t] += x;
        __syncthreads();
    }
    if (i < NN) g_row[br][i] = s[t] - v;             // exclusive within block
    if (t == 1023) g_bsum[br][blockIdx.x] = s[t];    // block total
}

__global__ void scan2() {
    int br = blockIdx.x;
    int t = threadIdx.x;   // 128
    int v = (t < 98) ? g_bsum[br][t] : 0;
    __shared__ int s[128];
    s[t] = v;
    __syncthreads();
    for (int off = 1; off < 128; off <<= 1) {
        int x = (t >= off) ? s[t - off] : 0;
        __syncthreads();
        s[t] += x;
        __syncthreads();
    }
    if (t < 98) g_bsum[br][t] = s[t] - v;            // exclusive
}

__global__ void scan3() {
    int i = blockIdx.x * 256 + threadIdx.x;
    if (i == 0) { g_row[0][NN] = ET; g_row[1][NN] = ET; }
    if (i >= 2 * NN) return;
    int br = i / NN, j = i - br * NN;
    int r = g_row[br][j] + g_bsum[br][j >> 10];
    g_row[br][j] = r;
    g_cur[br][j] = r;
}

__global__ void scatter_csr() {
    int i = blockIdx.x * 256 + threadIdx.x;
    if (i >= 2 * ET) return;
    int br = i / ET, e = i - br * ET;
    int d = g_dst[br][e];
    int pos = atomicAdd(&g_cur[br][d], 1);
    g_csr_src[br][pos] = g_src[br][e];
    g_csr_eid[br][pos] = e;
}

// att: per-node attention logits; c==0 lanes also reset the segment-softmax cells
__global__ void att_kernel(const float* __restrict__ aw_src, const float* __restrict__ aw_dst) {
    int n = blockIdx.x, t = threadIdx.x;
    __shared__ float rs[256], rd[256];
    float v = g_xh[(size_t)n * 256 + t];
    rs[t] = v * aw_src[t];
    rd[t] = v * aw_dst[t];
    __syncthreads();
    int h = t >> 7, c = t & 127;
    for (int st = 64; st > 0; st >>= 1) {
        if (c < st) { rs[t] += rs[t + st]; rd[t] += rd[t + st]; }
        __syncthreads();
    }
    if (c == 0) {
        g_asrc[n * 2 + h] = rs[t];
        g_adst[n * 2 + h] = rd[t];
        g_mmax[n * 2 + h] = 0u;
        g_den[n * 2 + h] = 0.f;
    }
}

__device__ __forceinline__ unsigned enc_f(float v) {
    unsigned u = __float_as_uint(v);
    return (u & 0x80000000u) ? ~u : (u | 0x80000000u);
}
__device__ __forceinline__ float dec_f(unsigned e) {
    unsigned u = (e & 0x80000000u) ? (e ^ 0x80000000u) : ~e;
    return __uint_as_float(u);
}

__global__ void edge_passA(int br) {
    int e = blockIdx.x * 256 + threadIdx.x;
    if (e >= ET) return;
    int s = g_src[br][e], d = g_dst[br][e];
#pragma unroll
    for (int h = 0; h < 2; h++) {
        float v = g_asrc[s * 2 + h] + g_adst[d * 2 + h];
        v = v > 0.f ? v : 0.2f * v;
        g_eval[e * 2 + h] = v;
        atomicMax(&g_mmax[d * 2 + h], enc_f(v));
    }
}

__global__ void edge_passB(int br) {
    int e = blockIdx.x * 256 + threadIdx.x;
    if (e >= ET) return;
    int d = g_dst[br][e];
#pragma unroll
    for (int h = 0; h < 2; h++) {
        float m = dec_f(g_mmax[d * 2 + h]);
        float ex = expf(g_eval[e * 2 + h] - m);
        g_eval[e * 2 + h] = ex;
        atomicAdd(&g_den[d * 2 + h], ex);
    }
}

// CSR gather: one block per dst node, no atomics.
__global__ __launch_bounds__(256) void edge_gather(int br) {
    int n = blockIdx.x;
    int t = threadIdx.x;
    int h = t >> 7;
    int beg = g_row[br][n], end = g_row[br][n + 1];
    float dinv = 1.f / (g_den[n * 2 + h] + 1e-16f);
    float acc = 0.f;
    for (int i = beg; i < end; i++) {
        int s = g_csr_src[br][i];
        int e = g_csr_eid[br][i];
        acc += g_eval[e * 2 + h] * g_xh[(size_t)s * 256 + t];
    }
    g_gat[(size_t)n * 256 + t] = acc * dinv;
}

// finalize: br==1 also produces next layer's mean (br0's output for this layer is already in g_xs)
__global__ void finalize_conv(int br, int layer, const float* __restrict__ bias) {
    int idx = blockIdx.x * 256 + threadIdx.x;
    if (idx >= NN * HID) return;
    int n = idx >> 7, c = idx & 127;
    float gm = 0.5f * (g_gat[(size_t)n * 256 + c] + g_gat[(size_t)n * 256 + 128 + c]) + bias[c];
    float v = g_mean[idx] + fmaxf(gm, 0.f);
    g_xs[br][layer][idx] = v;
    g_xstf[br][layer][idx] = f2tf(v);
    if (br == 1) g_mean[idx] = 0.5f * (g_xs[0][layer][idx] + v);
}

__global__ void clear_hc() {
    int idx = blockIdx.x * 256 + threadIdx.x;
    if (idx >= NN * H2) return;
    g_h[idx] = 0.f;
    g_c[idx] = 0.f;
    g_htf[idx] = 0u;
}

__global__ void gate_kernel(const float* __restrict__ bih, const float* __restrict__ bhh,
                            const float* __restrict__ attw, int l, int first) {
    int n = blockIdx.x;
    int j = threadIdx.x;  // 192
    size_t gb = (size_t)n * G4;
    float gi = g_G[gb + j]          + bih[j]          + bhh[j];
    float gf = g_G[gb + H2 + j]     + bih[H2 + j]     + bhh[H2 + j];
    float gg = g_G[gb + 2 * H2 + j] + bih[2 * H2 + j] + bhh[2 * H2 + j];
    float go = g_G[gb + 3 * H2 + j] + bih[3 * H2 + j] + bhh[3 * H2 + j];
    size_t hb = (size_t)n * H2 + j;
    float c = g_c[hb];
    c = sigm(gf) * c + sigm(gi) * tanhf(gg);
    float h = sigm(go) * tanhf(c);
    g_c[hb] = c;
    g_h[hb] = h;
    g_htf[hb] = f2tf(h);

    float part = h * attw[j];
#pragma unroll
    for (int o = 16; o; o >>= 1) part += __shfl_down_sync(0xffffffffu, part, o);
    __shared__ float ws[6];
    if ((j & 31) == 0) ws[j >> 5] = part;
    __syncthreads();
    if (j == 0) {
        float v = ws[0] + ws[1] + ws[2] + ws[3] + ws[4] + ws[5];
        if (first) g_s[l * NN + n] = v;
        else g_s[l * NN + n] += v;
    }
}

__global__ void jk_kernel(int br) {
    int idx = blockIdx.x * 256 + threadIdx.x;
    if (idx >= NN * HID) return;
    int n = idx >> 7;
    float s0 = g_s[n], s1 = g_s[NN + n], s2 = g_s[2 * NN + n];
    float m = fmaxf(s0, fmaxf(s1, s2));
    float e0 = expf(s0 - m), e1 = expf(s1 - m), e2 = expf(s2 - m);
    float inv = 1.f / (e0 + e1 + e2);
    float v = (e0 * g_xs[br][0][idx] + e1 * g_xs[br][1][idx] + e2 * g_xs[br][2][idx]) * inv;
    g_jk[br][idx] = v;
    g_jktf[br][idx] = f2tf(v);
}

__global__ void final_kernel(const float* __restrict__ lastW, float* __restrict__ out) {
    int n = blockIdx.x, c = threadIdx.x;  // 128
    __shared__ float red[4][129];
    size_t base = (size_t)n * HID + c;
    float w = lastW[c];
    float o0 = g_outs[0][base], o1 = g_outs[1][base], o2 = g_outs[2][base], o3 = g_outs[3][base];
    red[0][c] = o0 * w; red[1][c] = o1 * w; red[2][c] = o2 * w; red[3][c] = o3 * w;
    __syncthreads();
    for (int st = 64; st > 0; st >>= 1) {
        if (c < st) {
            red[0][c] += red[0][c + st];
            red[1][c] += red[1][c + st];
            red[2][c] += red[2][c + st];
            red[3][c] += red[3][c + st];
        }
        __syncthreads();
    }
    float z0 = red[0][0], z1 = red[1][0], z2 = red[2][0], z3 = red[3][0];
    float m = fmaxf(fmaxf(z0, z1), fmaxf(z2, z3));
    float e0 = expf(z0 - m), e1 = expf(z1 - m), e2 = expf(z2 - m), e3 = expf(z3 - m);
    float inv = 1.f / (e0 + e1 + e2 + e3);
    out[base] = (e0 * o0 + e1 * o1 + e2 * o2 + e3 * o3) * inv;
}

// ------------------------- host orchestration -------------------------
extern "C" void kernel_launch(void* const* d_in, const int* in_sizes, int n_in,
                              void* d_out, int out_size) {
    (void)in_sizes; (void)n_in; (void)out_size;
    const int*   x_idx    = (const int*)d_in[0];
    const float* x_flt    = (const float*)d_in[1];
    const int*   ei_l     = (const int*)d_in[2];
    const int*   ei_r     = (const int*)d_in[3];
    const float* emb_aa   = (const float*)d_in[4];
    const float* emb_ss   = (const float*)d_in[5];
    const float* conv_W   = (const float*)d_in[6];
    const float* c_asrc   = (const float*)d_in[7];
    const float* c_adst   = (const float*)d_in[8];
    const float* conv_b   = (const float*)d_in[9];
    const float* Wih      = (const float*)d_in[10];
    const float* Whh      = (const float*)d_in[11];
    const float* bih      = (const float*)d_in[12];
    const float* bhh      = (const float*)d_in[13];
    const float* jkW      = (const float*)d_in[14];
    /* d_in[15] jk_att_b cancels in softmax */
    const float* dW       = (const float*)d_in[16];
    const float* dB       = (const float*)d_in[17];
    const float* fW       = (const float*)d_in[18];
    const float* fB       = (const float*)d_in[19];
    const float* lW       = (const float*)d_in[20];
    float* out = (float*)d_out;

    void* tp;
    float *p_xh, *p_G, *p_h, *p_jk, *p_sq, *p_outs;
    unsigned *p_x0tf, *p_xstf, *p_htf, *p_jktf, *p_sqtf, *p_Wtf;
    cudaGetSymbolAddress(&tp, g_xh);    p_xh   = (float*)tp;
    cudaGetSymbolAddress(&tp, g_G);     p_G    = (float*)tp;
    cudaGetSymbolAddress(&tp, g_h);     p_h    = (float*)tp;
    cudaGetSymbolAddress(&tp, g_jk);    p_jk   = (float*)tp;
    cudaGetSymbolAddress(&tp, g_sq);    p_sq   = (float*)tp;
    cudaGetSymbolAddress(&tp, g_outs);  p_outs = (float*)tp;
    cudaGetSymbolAddress(&tp, g_x0tf);  p_x0tf = (unsigned*)tp;
    cudaGetSymbolAddress(&tp, g_xstf);  p_xstf = (unsigned*)tp;
    cudaGetSymbolAddress(&tp, g_htf);   p_htf  = (unsigned*)tp;
    cudaGetSymbolAddress(&tp, g_jktf);  p_jktf = (unsigned*)tp;
    cudaGetSymbolAddress(&tp, g_sqtf);  p_sqtf = (unsigned*)tp;
    cudaGetSymbolAddress(&tp, g_Wtf);   p_Wtf  = (unsigned*)tp;

    // raise dynamic smem limit for GEMM instantiations (host-side attr, capture-safe)
    cudaFuncSetAttribute((const void*)tgemm2<0,0,0,0>, cudaFuncAttributeMaxDynamicSharedMemorySize, GEMM_SMEM);
    cudaFuncSetAttribute((const void*)tgemm2<1,0,0,0>, cudaFuncAttributeMaxDynamicSharedMemorySize, GEMM_SMEM);
    cudaFuncSetAttribute((const void*)tgemm2<1,1,0,0>, cudaFuncAttributeMaxDynamicSharedMemorySize, GEMM_SMEM);
    cudaFuncSetAttribute((const void*)tgemm2<0,0,1,1>, cudaFuncAttributeMaxDynamicSharedMemorySize, GEMM_SMEM);
    cudaFuncSetAttribute((const void*)tgemm2<0,0,1,0>, cudaFuncAttributeMaxDynamicSharedMemorySize, GEMM_SMEM);

    const size_t NH = (size_t)NN * HID;

    // ---- weight conversion ----
    conv_tf_kernel<<<(SZ_CONV + 255) / 256, 256>>>(conv_W, p_Wtf + OFF_CONV, SZ_CONV);
    conv_tf_kernel<<<(SZ_WIH + 255) / 256, 256>>>(Wih, p_Wtf + OFF_WIH, SZ_WIH);
    conv_tf_kernel<<<(SZ_WHH + 255) / 256, 256>>>(Whh, p_Wtf + OFF_WHH, SZ_WHH);
    conv_tf_kernel<<<(SZ_DW + 255) / 256, 256>>>(dW, p_Wtf + OFF_DW, SZ_DW);
    conv_tf_kernel<<<(SZ_FW + 255) / 256, 256>>>(fW, p_Wtf + OFF_FW, SZ_FW);

    // ---- embeddings (+ layer-0 mean) + edges + CSR ----
    embed_kernel<<<(2 * NN * HID + 255) / 256, 256>>>(x_idx, x_flt, emb_aa, emb_ss);
    zero_cnt<<<(2 * NN + 255) / 256, 256>>>();
    build_edges<<<(ET + 255) / 256, 256>>>(ei_l, ei_r);
    { dim3 g((NN + 1023) / 1024, 2); scan1<<<g, 1024>>>(); }
    scan2<<<2, 128>>>();
    scan3<<<(2 * NN + 255) / 256, 256>>>();
    scatter_csr<<<(2 * ET + 255) / 256, 256>>>();

    // ---- 3 GAT layers, 2 branches (mean produced by previous layer's br=1 finalize) ----
    for (int layer = 0; layer < 3; layer++) {
        for (int br = 0; br < 2; br++) {
            const unsigned* xtf = (layer == 0) ? (p_x0tf + (size_t)br * NH)
                                               : (p_xstf + (size_t)(br * 3 + layer - 1) * NH);
            int li = br * 3 + layer;
            {
                dim3 grid(256 / 128, (NN + 127) / 128);
                tgemm2<0,0,0,0><<<grid, 256, GEMM_SMEM>>>(
                    xtf, p_Wtf + OFF_CONV + (size_t)li * HID * 256, nullptr, p_xh, nullptr,
                    NN, 256, HID);
            }
            att_kernel<<<NN, 256>>>(c_asrc + (size_t)li * 256, c_adst + (size_t)li * 256);
            edge_passA<<<(ET + 255) / 256, 256>>>(br);
            edge_passB<<<(ET + 255) / 256, 256>>>(br);
            edge_gather<<<NN, 256>>>(br);
            finalize_conv<<<(NN * HID + 255) / 256, 256>>>(br, layer, conv_b + (size_t)li * HID);
        }
    }

    // ---- JK bi-LSTM per branch ----
    for (int br = 0; br < 2; br++) {
        for (int dir = 0; dir < 2; dir++) {
            clear_hc<<<(NN * H2 + 255) / 256, 256>>>();
            const unsigned* wih = p_Wtf + OFF_WIH + (size_t)(br * 2 + dir) * G4 * HID;
            const unsigned* whh = p_Wtf + OFF_WHH + (size_t)(br * 2 + dir) * G4 * H2;
            const float* bi = bih + (size_t)(br * 2 + dir) * G4;
            const float* bh = bhh + (size_t)(br * 2 + dir) * G4;
            const float* aw = jkW + (size_t)br * (2 * H2) + (size_t)dir * H2;
            for (int st = 0; st < 3; st++) {
                int l = dir ? (2 - st) : st;
                dim3 grid(G4 / 128, (NN + 127) / 128);
                tgemm2<1,0,0,0><<<grid, 256, GEMM_SMEM>>>(
                    p_xstf + (size_t)(br * 3 + l) * NH, wih, nullptr, p_G, nullptr,
                    NN, G4, HID);
                tgemm2<1,1,0,0><<<grid, 256, GEMM_SMEM>>>(
                    p_htf, whh, nullptr, p_G, nullptr, NN, G4, H2);
                gate_kernel<<<NN, H2>>>(bi, bh, aw, l, dir == 0 ? 1 : 0);
            }
        }
        jk_kernel<<<(NN * HID + 255) / 256, 256>>>(br);
        {
            dim3 grid(HID / 128, (NN + 127) / 128);
            tgemm2<0,0,1,1><<<grid, 256, GEMM_SMEM>>>(
                p_jktf + (size_t)br * NH, p_Wtf + OFF_DW + (size_t)br * HID * HID,
                dB + (size_t)br * HID, p_sq + (size_t)br * NH, p_sqtf + (size_t)br * NH,
                NN, HID, HID);
        }
    }

    // ---- final projections + attention mix ----
    const unsigned* featA[4] = { p_jktf, p_sqtf, p_jktf + NH, p_sqtf + NH };
    for (int i = 0; i < 4; i++) {
        dim3 grid(HID / 128, (NN + 127) / 128);
        tgemm2<0,0,1,0><<<grid, 256, GEMM_SMEM>>>(
            featA[i], p_Wtf + OFF_FW + (size_t)i * HID * HID, fB + (size_t)i * HID,
            p_outs + (size_t)i * NH, nullptr, NN, HID, HID);
    }
    final_kernel<<<NN, HID>>>(lW, out);
}